// round 5
// baseline (speedup 1.0000x reference)
#include <cuda_runtime.h>
#include <cstdint>

// SingleHeadAttention: O = softmax(Q K^T) V, no scaling, fp32.
// SQ = SK = 8192, D = 128.
// Flash-attention, fp32 via packed fma.rn.f32x2 (FFMA2).
// BQ=64, BK=128, 256 threads, 1 CTA/SM, grid = 128.
// V prefetched via cp.async during S-phase; K_{t+1} prefetched into
// registers during PV-phase (Kst dead there), STS'd at PV tail with a
// conflict-free 8k x 16d per-warp transpose mapping.
// P stored transposed+duplicated (Pd[k][2q]=Pd[k][2q+1]) so the PV loop
// reads broadcast multiplier pairs with a single LDS.64 (no MOV dup).

#define TSQ 8192
#define TSK 8192
#define TD  128
#define BQ  64
#define BK  128
#define NTHREADS 256

// smem strides (floats)
#define QS_STRIDE  130   // Qs[q][d]   : float2 stores, scalar broadcast reads
#define KST_STRIDE 130   // Kst[d][k]  : transposed, LDS.64 k-pair reads (even => 8B aligned)
#define VS_STRIDE  128   // Vs[k][d]   : cp.async rows, LDS.64 d-pair reads (bank spread via 2tx)
#define PD_STRIDE  130   // Pd[k][2q dup] : STS.64 (p,p) writes, LDS.64 dup-pair reads

#define QS_FLOATS  (BQ * QS_STRIDE)    // 8320
#define KST_FLOATS (TD * KST_STRIDE)   // 16640
#define VS_FLOATS  (BK * VS_STRIDE)    // 16384
#define PD_FLOATS  (BK * PD_STRIDE)    // 16640
#define SMEM_FLOATS (QS_FLOATS + KST_FLOATS + VS_FLOATS + PD_FLOATS)
#define SMEM_BYTES  (SMEM_FLOATS * 4)  // 231936 bytes (< 232448 cap)

typedef unsigned long long ull;

// ---- packed f32x2 helpers (sm_103a FFMA2 path) ----
__device__ __forceinline__ ull dup2(float x) {
    ull r;
    asm("mov.b64 %0, {%1, %1};" : "=l"(r) : "f"(x));
    return r;
}
__device__ __forceinline__ void fma2(ull& d, ull a, ull b) {
    asm("fma.rn.f32x2 %0, %1, %2, %0;" : "+l"(d) : "l"(a), "l"(b));
}
__device__ __forceinline__ ull mul2(ull a, ull b) {
    ull r;
    asm("mul.rn.f32x2 %0, %1, %2;" : "=l"(r) : "l"(a), "l"(b));
    return r;
}
__device__ __forceinline__ float2 u2f(ull v) {
    float2 f;
    asm("mov.b64 {%0, %1}, %2;" : "=f"(f.x), "=f"(f.y) : "l"(v));
    return f;
}
// ---- cp.async 16B (LDGSTS) ----
__device__ __forceinline__ void cp16(uint32_t dst_smem, const void* src_gmem) {
    asm volatile("cp.async.cg.shared.global [%0], [%1], 16;"
                 :: "r"(dst_smem), "l"(src_gmem) : "memory");
}
__device__ __forceinline__ void cp_commit() {
    asm volatile("cp.async.commit_group;" ::: "memory");
}
__device__ __forceinline__ void cp_wait0() {
    asm volatile("cp.async.wait_group 0;" ::: "memory");
}

__global__ void __launch_bounds__(NTHREADS, 1)
attn_kernel(const float* __restrict__ Q,
            const float* __restrict__ K,
            const float* __restrict__ V,
            float* __restrict__ O)
{
    extern __shared__ float smem[];
    float* Qs  = smem;                 // [BQ][QS_STRIDE]
    float* Kst = Qs  + QS_FLOATS;      // [TD][KST_STRIDE]  (K transposed)
    float* Vs  = Kst + KST_FLOATS;     // [BK][VS_STRIDE]
    float* Pd  = Vs  + VS_FLOATS;      // [BK][PD_STRIDE]   (P transposed, duplicated)

    const int tid  = threadIdx.x;
    const int w    = tid >> 5;
    const int lane = tid & 31;
    const int ty   = tid >> 4;   // 0..15 : owns q rows 4ty .. 4ty+3
    const int tx   = tid & 15;   // 0..15 : owns k/d pair columns 2tx+32j
    const int q0   = blockIdx.x * BQ;

    const uint32_t vs_base = (uint32_t)__cvta_generic_to_shared(Vs);

    // K-transpose job mapping (conflict-free STS):
    //   lane -> kl = lane>>2 (0..7), dq = lane&3 (0..3)
    //   job  -> kg = job>>3  (0..15), dg = job&7 (0..7)
    //   kr = kg*8 + kl, d0 = dg*16 + dq*4
    //   STS bank = (8dq + kl + 2c + 8kg) mod 32 -> distinct across warp.
    const int kl = lane >> 2;   // 0..7
    const int dq = lane & 3;    // 0..3

    // ---- load Q tile once: Qs[q][d] (float4 gmem loads, float2 smem stores) ----
    #pragma unroll
    for (int it = 0; it < 8; it++) {
        int idx = tid + it * NTHREADS;          // 0..2047 float4 slots
        int row = idx >> 5;                     // 0..63
        int col = idx & 31;                     // 0..31 (float4)
        float4 v = *reinterpret_cast<const float4*>(Q + (q0 + row) * TD + col * 4);
        float* dst = Qs + row * QS_STRIDE + col * 4;
        *reinterpret_cast<float2*>(dst)     = make_float2(v.x, v.y);
        *reinterpret_cast<float2*>(dst + 2) = make_float2(v.z, v.w);
    }

    // ---- prologue: load K_0 transposed ----
    #pragma unroll
    for (int jt = 0; jt < 16; jt++) {
        int job = jt * 8 + w;               // 0..127
        int kg  = job >> 3;                 // 0..15
        int dg  = job & 7;                  // 0..7
        int kr  = kg * 8 + kl;              // 0..127
        int d0  = dg * 16 + dq * 4;         // 0..124
        float4 v = *reinterpret_cast<const float4*>(K + kr * TD + d0);
        Kst[(d0 + 0) * KST_STRIDE + kr] = v.x;
        Kst[(d0 + 1) * KST_STRIDE + kr] = v.y;
        Kst[(d0 + 2) * KST_STRIDE + kr] = v.z;
        Kst[(d0 + 3) * KST_STRIDE + kr] = v.w;
    }
    __syncthreads();

    // per-row online softmax state (replicated across 16-lane row groups)
    float m[4], l[4];
    ull o2[4][4];                               // O accum: 4 q-rows x 4 d-pairs
    #pragma unroll
    for (int i = 0; i < 4; i++) {
        m[i] = -1e30f;
        l[i] = 0.0f;
        #pragma unroll
        for (int j = 0; j < 4; j++) o2[i][j] = 0ull;
    }

    for (int t = 0; t < TSK / BK; t++) {
        const int kbase = t * BK;

        // ---- issue cp.async for V_t (Vs free: PV_{t-1} done at loop-end barrier) ----
        #pragma unroll
        for (int it = 0; it < 16; it++) {
            int r = it * 8 + w;                 // 0..127
            cp16(vs_base + (uint32_t)(r * VS_STRIDE + lane * 4) * 4u,
                 V + (kbase + r) * TD + lane * 4);
        }
        cp_commit();

        // ---- S = Q K^T : s2[i][j] packs k-pair (2tx+32j, 2tx+32j+1) ----
        ull s2[4][4];
        #pragma unroll
        for (int i = 0; i < 4; i++)
            #pragma unroll
            for (int j = 0; j < 4; j++) s2[i][j] = 0ull;

        #pragma unroll 4
        for (int kk = 0; kk < TD; kk++) {
            const float* krow = Kst + kk * KST_STRIDE + 2 * tx;
            ull k0 = *reinterpret_cast<const ull*>(krow);
            ull k1 = *reinterpret_cast<const ull*>(krow + 32);
            ull k2 = *reinterpret_cast<const ull*>(krow + 64);
            ull k3 = *reinterpret_cast<const ull*>(krow + 96);
            #pragma unroll
            for (int i = 0; i < 4; i++) {
                ull qd = dup2(Qs[(ty * 4 + i) * QS_STRIDE + kk]);
                fma2(s2[i][0], qd, k0);
                fma2(s2[i][1], qd, k1);
                fma2(s2[i][2], qd, k2);
                fma2(s2[i][3], qd, k3);
            }
        }

        // ---- online softmax; write Pd[k][2q dup] ----
        #pragma unroll
        for (int i = 0; i < 4; i++) {
            float2 f0 = u2f(s2[i][0]);
            float2 f1 = u2f(s2[i][1]);
            float2 f2 = u2f(s2[i][2]);
            float2 f3 = u2f(s2[i][3]);
            float rm = fmaxf(fmaxf(fmaxf(f0.x, f0.y), fmaxf(f1.x, f1.y)),
                             fmaxf(fmaxf(f2.x, f2.y), fmaxf(f3.x, f3.y)));
            #pragma unroll
            for (int off = 8; off >= 1; off >>= 1)
                rm = fmaxf(rm, __shfl_xor_sync(0xffffffffu, rm, off));
            float mn    = fmaxf(m[i], rm);
            float scale = __expf(m[i] - mn);
            float p0 = __expf(f0.x - mn), p1 = __expf(f0.y - mn);
            float p2 = __expf(f1.x - mn), p3 = __expf(f1.y - mn);
            float p4 = __expf(f2.x - mn), p5 = __expf(f2.y - mn);
            float p6 = __expf(f3.x - mn), p7 = __expf(f3.y - mn);
            float rs = ((p0 + p1) + (p2 + p3)) + ((p4 + p5) + (p6 + p7));
            #pragma unroll
            for (int off = 8; off >= 1; off >>= 1)
                rs += __shfl_xor_sync(0xffffffffu, rs, off);
            l[i] = l[i] * scale + rs;
            m[i] = mn;

            // Pd[k][2q], Pd[k][2q+1] = p   (k = 2tx+c+32j, q = 4ty+i)
            const int qc = 8 * ty + 2 * i;
            float* pb = Pd + (2 * tx) * PD_STRIDE + qc;
            *reinterpret_cast<float2*>(pb)                  = make_float2(p0, p0);
            *reinterpret_cast<float2*>(pb + PD_STRIDE)      = make_float2(p1, p1);
            *reinterpret_cast<float2*>(pb + 32 * PD_STRIDE) = make_float2(p2, p2);
            *reinterpret_cast<float2*>(pb + 33 * PD_STRIDE) = make_float2(p3, p3);
            *reinterpret_cast<float2*>(pb + 64 * PD_STRIDE) = make_float2(p4, p4);
            *reinterpret_cast<float2*>(pb + 65 * PD_STRIDE) = make_float2(p5, p5);
            *reinterpret_cast<float2*>(pb + 96 * PD_STRIDE) = make_float2(p6, p6);
            *reinterpret_cast<float2*>(pb + 97 * PD_STRIDE) = make_float2(p7, p7);

            ull sc = dup2(scale);
            #pragma unroll
            for (int j = 0; j < 4; j++) o2[i][j] = mul2(o2[i][j], sc);
        }

        cp_wait0();           // V_t landed (this thread's chunks)
        __syncthreads();      // B1: V_t + Pd visible to all; S_t done (Kst free)

        // ---- prefetch K_{t+1} into registers (Kst dead during PV) ----
        const int kb_next = (t + 1 < TSK / BK) ? kbase + BK : 0;
        float4 kreg[16];
        #pragma unroll
        for (int jt = 0; jt < 16; jt++) {
            int job = jt * 8 + w;
            int kr  = (job >> 3) * 8 + kl;
            int d0  = (job & 7) * 16 + dq * 4;
            kreg[jt] = *reinterpret_cast<const float4*>(K + (kb_next + kr) * TD + d0);
        }

        // ---- O += P V : dup'd P pairs via single LDS.64 each ----
        const float* pdq = Pd + 8 * ty;         // dup'd pair base for this thread's rows
        #pragma unroll 2
        for (int kk = 0; kk < BK; kk++) {
            const float* vrow = Vs + kk * VS_STRIDE + 2 * tx;
            ull v0 = *reinterpret_cast<const ull*>(vrow);
            ull v1 = *reinterpret_cast<const ull*>(vrow + 32);
            ull v2 = *reinterpret_cast<const ull*>(vrow + 64);
            ull v3 = *reinterpret_cast<const ull*>(vrow + 96);
            const float* prow = pdq + kk * PD_STRIDE;
            #pragma unroll
            for (int i = 0; i < 4; i++) {
                ull pd = *reinterpret_cast<const ull*>(prow + 2 * i);
                fma2(o2[i][0], pd, v0);
                fma2(o2[i][1], pd, v1);
                fma2(o2[i][2], pd, v2);
                fma2(o2[i][3], pd, v3);
            }
        }

        // ---- commit K_{t+1} transpose to smem (conflict-free mapping) ----
        #pragma unroll
        for (int jt = 0; jt < 16; jt++) {
            int job = jt * 8 + w;
            int kr  = (job >> 3) * 8 + kl;
            int d0  = (job & 7) * 16 + dq * 4;
            Kst[(d0 + 0) * KST_STRIDE + kr] = kreg[jt].x;
            Kst[(d0 + 1) * KST_STRIDE + kr] = kreg[jt].y;
            Kst[(d0 + 2) * KST_STRIDE + kr] = kreg[jt].z;
            Kst[(d0 + 3) * KST_STRIDE + kr] = kreg[jt].w;
        }
        __syncthreads();      // B2: Kst = K_{t+1} ready; Vs/Pd free
    }

    // ---- epilogue: normalize and store ----
    #pragma unroll
    for (int i = 0; i < 4; i++) {
        float inv = 1.0f / l[i];
        int q = q0 + ty * 4 + i;
        #pragma unroll
        for (int jj = 0; jj < 4; jj++) {
            float2 f = u2f(o2[i][jj]);
            f.x *= inv;
            f.y *= inv;
            *reinterpret_cast<float2*>(O + q * TD + 2 * tx + 32 * jj) = f;
        }
    }
}

extern "C" void kernel_launch(void* const* d_in, const int* in_sizes, int n_in,
                              void* d_out, int out_size) {
    const float* Q = (const float*)d_in[0];
    const float* K = (const float*)d_in[1];
    const float* V = (const float*)d_in[2];
    float* O = (float*)d_out;

    cudaFuncSetAttribute(attn_kernel,
                         cudaFuncAttributeMaxDynamicSharedMemorySize, SMEM_BYTES);
    attn_kernel<<<TSQ / BQ, NTHREADS, SMEM_BYTES>>>(Q, K, V, O);
}

// round 11
// speedup vs baseline: 1.2055x; 1.2055x over previous
#include <cuda_runtime.h>
#include <cstdint>

// SingleHeadAttention: O = softmax(Q K^T) V, no scaling, fp32.
// SQ = SK = 8192, D = 128.  Flash attention, FFMA2 (fma.rn.f32x2).
// BQ=64, BK=128, 256 threads, 1 CTA/SM, grid = 128.
//
// Crossbar-optimized layout:
//  - S-phase: warp w owns k-slice [16w,16w+16); K natural layout (cp.async),
//    read as LDS.128 d-chunks. Q transposed once into Qst[d][q] with 12-float
//    q-group spacing -> conflict-free LDS.128 giving packed q-pair operands.
//  - softmax: split-k partial max/sum per warp + smem combine (running m,l).
//  - PV-phase: warp w owns d-slice [16w,16w+16); V read via 1 LDS.128/kk;
//    P stored pair-packed (same 12-spaced layout) -> ulonglong2 operands.

#define TSQ 8192
#define TSK 8192
#define TD  128
#define BQ  64
#define BK  128
#define NTHREADS 256
#define TILES (TSK / BK)   // 64

#define QST_STRIDE 92      // Qst[d][col12(q)]
#define KS_STRIDE  132     // Ks[k][d] natural
#define VS_STRIDE  128     // Vs[k][d] natural
#define P_STRIDE   92      // P[k][col12(q)]

#define QST_OFF   0
#define KS_OFF    (QST_OFF + TD * QST_STRIDE)   // 11776
#define VS_OFF    (KS_OFF + BK * KS_STRIDE)     // 28672
#define P_OFF     (VS_OFF + BK * VS_STRIDE)     // 45056
#define PMAX_OFF  (P_OFF + BK * P_STRIDE)       // 56832  (row 0 reused as m_new)
#define PSUM_OFF  (PMAX_OFF + 8 * 64)           // 57344
#define MRUN_OFF  (PSUM_OFF + 8 * 64)           // 57856
#define LRUN_OFF  (MRUN_OFF + 64)               // 57920
#define SCALE_OFF (LRUN_OFF + 64)               // 57984
#define SMEM_FLOATS (SCALE_OFF + 64)            // 58048
#define SMEM_BYTES  (SMEM_FLOATS * 4)           // 232192 (< 232448 cap)

typedef unsigned long long ull;

__device__ __forceinline__ ull dup2(float x) {
    ull r; asm("mov.b64 %0, {%1, %1};" : "=l"(r) : "f"(x)); return r;
}
__device__ __forceinline__ ull pack2(float a, float b) {
    ull r; asm("mov.b64 %0, {%1, %2};" : "=l"(r) : "f"(a), "f"(b)); return r;
}
__device__ __forceinline__ void fma2(ull& d, ull a, ull b) {
    asm("fma.rn.f32x2 %0, %1, %2, %0;" : "+l"(d) : "l"(a), "l"(b));
}
__device__ __forceinline__ ull mul2(ull a, ull b) {
    ull r; asm("mul.rn.f32x2 %0, %1, %2;" : "=l"(r) : "l"(a), "l"(b)); return r;
}
__device__ __forceinline__ float2 u2f(ull v) {
    float2 f; asm("mov.b64 {%0, %1}, %2;" : "=f"(f.x), "=f"(f.y) : "l"(v)); return f;
}
__device__ __forceinline__ void cp16(uint32_t dst_smem, const void* src_gmem) {
    asm volatile("cp.async.cg.shared.global [%0], [%1], 16;"
                 :: "r"(dst_smem), "l"(src_gmem) : "memory");
}
__device__ __forceinline__ void cp_commit() {
    asm volatile("cp.async.commit_group;" ::: "memory");
}
__device__ __forceinline__ void cp_wait1() {
    asm volatile("cp.async.wait_group 1;" ::: "memory");
}
__device__ __forceinline__ void cp_wait0() {
    asm volatile("cp.async.wait_group 0;" ::: "memory");
}

// col12(q) = 12*(q>>3) + (q&7): 8-float q groups at 12-float spacing so that
// 8 group-chunks land on disjoint bank quads (12*qg mod 32 = {0,12,24,4,16,28,8,20}).
__device__ __forceinline__ int col12(int q) { return 12 * (q >> 3) + (q & 7); }

__global__ void __launch_bounds__(NTHREADS, 1)
attn_kernel(const float* __restrict__ Q,
            const float* __restrict__ K,
            const float* __restrict__ V,
            float* __restrict__ O)
{
    extern __shared__ float smem[];
    float* Qst  = smem + QST_OFF;
    float* Ks   = smem + KS_OFF;
    float* Vs   = smem + VS_OFF;
    float* Pm   = smem + P_OFF;
    float* pmax = smem + PMAX_OFF;   // [8][64]; row 0 doubles as m_new after combine
    float* psum = smem + PSUM_OFF;   // [8][64]
    float* mrun = smem + MRUN_OFF;   // [64]
    float* lrun = smem + LRUN_OFF;   // [64]
    float* scl  = smem + SCALE_OFF;  // [64]

    const int tid  = threadIdx.x;
    const int w    = tid >> 5;       // warp 0..7 : k-slice (S), d-slice (PV)
    const int lane = tid & 31;
    const int qg   = lane >> 2;      // 0..7 : q group 8qg..8qg+7
    const int kg   = lane & 3;       // 0..3 : k (S) / d (PV) sub-index
    const int q0   = blockIdx.x * BQ;

    const uint32_t ks_base = (uint32_t)__cvta_generic_to_shared(Ks);
    const uint32_t vs_base = (uint32_t)__cvta_generic_to_shared(Vs);

    // ---- prologue: Q transpose into Qst (once) ----
    #pragma unroll
    for (int it = 0; it < 8; it++) {
        int idx  = tid + it * NTHREADS;      // 0..2047 float4 slots of Q tile
        int row  = idx >> 5;                 // q row 0..63
        int col4 = idx & 31;                 // d float4 0..31
        float4 v = *reinterpret_cast<const float4*>(Q + (q0 + row) * TD + col4 * 4);
        int c = col12(row);
        Qst[(col4 * 4 + 0) * QST_STRIDE + c] = v.x;
        Qst[(col4 * 4 + 1) * QST_STRIDE + c] = v.y;
        Qst[(col4 * 4 + 2) * QST_STRIDE + c] = v.z;
        Qst[(col4 * 4 + 3) * QST_STRIDE + c] = v.w;
    }
    // ---- prologue: issue K_0 then V_0 (group order: [K0, V0]) ----
    #pragma unroll
    for (int it = 0; it < 16; it++) {
        int c = tid + it * NTHREADS;         // 0..4095 16B chunks
        int row = c >> 5, col = c & 31;
        cp16(ks_base + (uint32_t)(row * KS_STRIDE + col * 4) * 4u,
             K + row * TD + col * 4);
    }
    cp_commit();
    #pragma unroll
    for (int it = 0; it < 16; it++) {
        int c = tid + it * NTHREADS;
        int row = c >> 5, col = c & 31;
        cp16(vs_base + (uint32_t)(row * VS_STRIDE + col * 4) * 4u,
             V + row * TD + col * 4);
    }
    cp_commit();
    if (tid < 64) { mrun[tid] = -1e30f; lrun[tid] = 0.0f; }
    cp_wait1();          // K_0 done (V_0 may still be in flight)
    __syncthreads();     // B0

    ull o2[4][4];        // O accum: [qpair i][d j], q = 8qg+2i(+1), d = 16w+4kg+j
    #pragma unroll
    for (int i = 0; i < 4; i++)
        #pragma unroll
        for (int j = 0; j < 4; j++) o2[i][j] = 0ull;

    for (int t = 0; t < TILES; t++) {
        // ================= S-phase: warp k-slice [16w,16w+16) =================
        // s2[i][j]: qpair (8qg+2i, +1) x k = 16w + kg + 4j
        ull s2[4][4];
        #pragma unroll
        for (int i = 0; i < 4; i++)
            #pragma unroll
            for (int j = 0; j < 4; j++) s2[i][j] = 0ull;

        {
            const float* krow0 = Ks + (16 * w + kg) * KS_STRIDE;
            const float* qcol  = Qst + 12 * qg;
            #pragma unroll 2
            for (int d0 = 0; d0 < TD; d0 += 4) {
                float4 kv[4];
                #pragma unroll
                for (int j = 0; j < 4; j++)
                    kv[j] = *reinterpret_cast<const float4*>(krow0 + (4 * j) * KS_STRIDE + d0);
                const float* kvf = reinterpret_cast<const float*>(kv);
                #pragma unroll
                for (int e = 0; e < 4; e++) {
                    const float* qrow = qcol + (d0 + e) * QST_STRIDE;
                    ulonglong2 qa = *reinterpret_cast<const ulonglong2*>(qrow);      // pairs i=0,1
                    ulonglong2 qb = *reinterpret_cast<const ulonglong2*>(qrow + 4);  // pairs i=2,3
                    #pragma unroll
                    for (int j = 0; j < 4; j++) {
                        ull kd = dup2(kvf[4 * j + e]);
                        fma2(s2[0][j], qa.x, kd);
                        fma2(s2[1][j], qa.y, kd);
                        fma2(s2[2][j], qb.x, kd);
                        fma2(s2[3][j], qb.y, kd);
                    }
                }
            }
        }

        // ---- warp-partial max over this warp's 16 k, per q ----
        #pragma unroll
        for (int i = 0; i < 4; i++) {
            float2 a = u2f(s2[i][0]), b = u2f(s2[i][1]);
            float2 c = u2f(s2[i][2]), d = u2f(s2[i][3]);
            float me = fmaxf(fmaxf(a.x, b.x), fmaxf(c.x, d.x));
            float mo = fmaxf(fmaxf(a.y, b.y), fmaxf(c.y, d.y));
            me = fmaxf(me, __shfl_xor_sync(0xffffffffu, me, 1));
            me = fmaxf(me, __shfl_xor_sync(0xffffffffu, me, 2));
            mo = fmaxf(mo, __shfl_xor_sync(0xffffffffu, mo, 1));
            mo = fmaxf(mo, __shfl_xor_sync(0xffffffffu, mo, 2));
            if (kg == 0)
                *reinterpret_cast<float2*>(pmax + w * 64 + 8 * qg + 2 * i) = make_float2(me, mo);
        }
        __syncthreads();  // B1: pmax ready; S reads of Ks done

        // ---- issue K_{t+1} (Ks now free) ----
        {
            const float* kn = K + ((t + 1 < TILES) ? (t + 1) * BK : 0) * TD;
            #pragma unroll
            for (int it = 0; it < 16; it++) {
                int c = tid + it * NTHREADS;
                int row = c >> 5, col = c & 31;
                cp16(ks_base + (uint32_t)(row * KS_STRIDE + col * 4) * 4u,
                     kn + row * TD + col * 4);
            }
            cp_commit();
        }

        // ---- stats combine (one thread per q) ----
        if (tid < 64) {
            int q = tid;
            float mold = mrun[q];
            float mx = mold;
            #pragma unroll
            for (int w2 = 0; w2 < 8; w2++) mx = fmaxf(mx, pmax[w2 * 64 + q]);
            scl[q]  = __expf(mold - mx);
            mrun[q] = mx;
            pmax[q] = mx;      // row 0 reused as m_new
        }
        __syncthreads();  // B2: m_new + scale ready

        // ---- P = exp(s - m_new); write P; warp-partial sums ----
        {
            float2 mn[4];
            #pragma unroll
            for (int i = 0; i < 4; i++)
                mn[i] = *reinterpret_cast<const float2*>(pmax + 8 * qg + 2 * i);

            float se[4], so[4];
            #pragma unroll
            for (int i = 0; i < 4; i++) { se[i] = 0.0f; so[i] = 0.0f; }
            #pragma unroll
            for (int i = 0; i < 4; i++)
                #pragma unroll
                for (int j = 0; j < 4; j++) {
                    float2 f = u2f(s2[i][j]);
                    float pe = __expf(f.x - mn[i].x);
                    float po = __expf(f.y - mn[i].y);
                    s2[i][j] = pack2(pe, po);
                    se[i] += pe; so[i] += po;
                }
            // store P rows: k = 16w + kg + 4j, cols 12qg..12qg+7
            #pragma unroll
            for (int j = 0; j < 4; j++) {
                float* pr = Pm + (16 * w + kg + 4 * j) * P_STRIDE + 12 * qg;
                ulonglong2 v0; v0.x = s2[0][j]; v0.y = s2[1][j];
                ulonglong2 v1; v1.x = s2[2][j]; v1.y = s2[3][j];
                *reinterpret_cast<ulonglong2*>(pr)     = v0;
                *reinterpret_cast<ulonglong2*>(pr + 4) = v1;
            }
            // partial sums across kg lanes
            #pragma unroll
            for (int i = 0; i < 4; i++) {
                float e = se[i], o = so[i];
                e += __shfl_xor_sync(0xffffffffu, e, 1);
                e += __shfl_xor_sync(0xffffffffu, e, 2);
                o += __shfl_xor_sync(0xffffffffu, o, 1);
                o += __shfl_xor_sync(0xffffffffu, o, 2);
                if (kg == 0)
                    *reinterpret_cast<float2*>(psum + w * 64 + 8 * qg + 2 * i) = make_float2(e, o);
            }
        }

        cp_wait1();       // V_t complete (K_{t+1} may still be in flight)
        __syncthreads();  // B3: P, psum, V_t visible

        // ---- l update (after B3: psum ready) ----
        if (tid < 64) {
            int q = tid;
            float s8 = 0.0f;
            #pragma unroll
            for (int w2 = 0; w2 < 8; w2++) s8 += psum[w2 * 64 + q];
            lrun[q] = lrun[q] * scl[q] + s8;
        }

        // ---- PV-phase: warp d-slice [16w,16w+16) ----
        {
            // rescale o2 by scale[q]
            #pragma unroll
            for (int i = 0; i < 4; i++) {
                float2 s = *reinterpret_cast<const float2*>(scl + 8 * qg + 2 * i);
                ull sc = pack2(s.x, s.y);
                #pragma unroll
                for (int j = 0; j < 4; j++) o2[i][j] = mul2(o2[i][j], sc);
            }
            const float* vcol = Vs + 16 * w + 4 * kg;
            const float* pcol = Pm + 12 * qg;
            #pragma unroll 2
            for (int kk = 0; kk < BK; kk++) {
                float4 vv = *reinterpret_cast<const float4*>(vcol + kk * VS_STRIDE);
                const float* pr = pcol + kk * P_STRIDE;
                ulonglong2 pa = *reinterpret_cast<const ulonglong2*>(pr);      // pairs i=0,1
                ulonglong2 pb = *reinterpret_cast<const ulonglong2*>(pr + 4);  // pairs i=2,3
                const float* vvf = reinterpret_cast<const float*>(&vv);
                #pragma unroll
                for (int j = 0; j < 4; j++) {
                    ull vd = dup2(vvf[j]);
                    fma2(o2[0][j], pa.x, vd);
                    fma2(o2[1][j], pa.y, vd);
                    fma2(o2[2][j], pb.x, vd);
                    fma2(o2[3][j], pb.y, vd);
                }
            }
        }
        __syncthreads();  // B4: PV done (P, Vs free; lrun update done)

        // ---- issue V_{t+1} (Vs free) ----
        {
            const float* vn = V + ((t + 1 < TILES) ? (t + 1) * BK : 0) * TD;
            #pragma unroll
            for (int it = 0; it < 16; it++) {
                int c = tid + it * NTHREADS;
                int row = c >> 5, col = c & 31;
                cp16(vs_base + (uint32_t)(row * VS_STRIDE + col * 4) * 4u,
                     vn + row * TD + col * 4);
            }
            cp_commit();
        }
        cp_wait1();       // K_{t+1} complete (V_{t+1} may pend)
        __syncthreads();  // B5: Ks = K_{t+1} visible to all
    }

    cp_wait0();           // drain last prefetch before exit

    // ---- epilogue: normalize and store ----
    #pragma unroll
    for (int i = 0; i < 4; i++) {
        float2 lv = *reinterpret_cast<const float2*>(lrun + 8 * qg + 2 * i);
        ull inv = pack2(1.0f / lv.x, 1.0f / lv.y);
        int qe = q0 + 8 * qg + 2 * i;
        #pragma unroll
        for (int j = 0; j < 4; j++) {
            float2 f = u2f(mul2(o2[i][j], inv));
            int d = 16 * w + 4 * kg + j;
            O[qe * TD + d]       = f.x;
            O[(qe + 1) * TD + d] = f.y;
        }
    }
}

extern "C" void kernel_launch(void* const* d_in, const int* in_sizes, int n_in,
                              void* d_out, int out_size) {
    const float* Q = (const float*)d_in[0];
    const float* K = (const float*)d_in[1];
    const float* V = (const float*)d_in[2];
    float* O = (float*)d_out;

    cudaFuncSetAttribute(attn_kernel,
                         cudaFuncAttributeMaxDynamicSharedMemorySize, SMEM_BYTES);
    attn_kernel<<<TSQ / BQ, NTHREADS, SMEM_BYTES>>>(Q, K, V, O);
}